// round 13
// baseline (speedup 1.0000x reference)
#include <cuda_runtime.h>
#include <cuda_fp16.h>
#include <cuda_bf16.h>
#include <cstdint>

#define NN   50000
#define EE   800000
#define ET   (EE + NN)
#define DIN  512
#define DH   128
#define DC   64
#define KIT  10
#define AL   0.1f
#define OMA  0.9f

#define NBF2 ((NN + 63) / 64)      // feature-diffusion blocks (8 warps x 8 nodes)
#define NBP  ((NN + 255) / 256)    // p-diffusion blocks
#define NSB  ((NN + 255) / 256)    // scan blocks (196)
#define G1B  ((NN + 255) / 256)    // gemm1 tiles, BM=256 (196)
#define DEGB ((EE + 255) / 256)    // deg blocks fused into wsplit (3125)
#define CPIT 313                   // copy blocks per diffusion iteration

#define LDP     40                 // padded smem row (elements); 80B rows
#define A_TILE  (256 * LDP * 2)    // 20480 B (one of Ah/Al)
#define B_TILE  (128 * LDP * 2)    // 10240 B (one of Bh/Bl)
#define BUF_B   (2 * A_TILE + 2 * B_TILE)   // 61440 B per buffer
#define G1_SMEM (2 * BUF_B)        // 122880 B double-buffered

typedef unsigned long long u64;

// ---------------- device scratch ----------------
// g_deg and g_fill are SELF-CLEANING: scan1 resets deg after reading,
// scan3 resets fill (before k_fill) — no init kernel needed per replay.
__device__ int     g_deg[NN];
__device__ float   g_dinv[NN];
__device__ int     g_rowptr[NN + 1];
__device__ int     g_fill[NN];
__device__ __align__(16) int2 g_cw[ET];
__device__ int     g_bsum[256];
__device__ __align__(16) __nv_bfloat16 g_Whi[DH * DIN];
__device__ __align__(16) __nv_bfloat16 g_Wlo[DH * DIN];
// 0/1 = ping-pong iterates, 2 = h0 (h1 after relu), all fp16
__device__ __half2 g_hb[3][(size_t)NN * (DH/2)];
__device__ float   g_p[2][NN];

// ---------------- helpers ----------------
__device__ __forceinline__ uint32_t s2u(const void* p) {
    uint32_t a;
    asm("{ .reg .u64 t; cvta.to.shared.u64 t, %1; cvt.u32.u64 %0, t; }" : "=r"(a) : "l"(p));
    return a;
}
__device__ __forceinline__ unsigned h2u(__half2 h) {
    unsigned u; *reinterpret_cast<__half2*>(&u) = h; return u;
}
__device__ __forceinline__ unsigned b2u(__nv_bfloat162 h) {
    unsigned u; *reinterpret_cast<__nv_bfloat162*>(&u) = h; return u;
}
__device__ __forceinline__ void ldsm4(unsigned* r, uint32_t addr) {
    asm volatile("ldmatrix.sync.aligned.m8n8.x4.shared.b16 {%0,%1,%2,%3}, [%4];"
        : "=r"(r[0]), "=r"(r[1]), "=r"(r[2]), "=r"(r[3]) : "r"(addr));
}
__device__ __forceinline__ void mma16816(float* c, const unsigned* a, const unsigned* b) {
    asm volatile("mma.sync.aligned.m16n8k16.row.col.f32.bf16.bf16.f32 "
        "{%0,%1,%2,%3}, {%4,%5,%6,%7}, {%8,%9}, {%0,%1,%2,%3};"
        : "+f"(c[0]), "+f"(c[1]), "+f"(c[2]), "+f"(c[3])
        : "r"(a[0]), "r"(a[1]), "r"(a[2]), "r"(a[3]), "r"(b[0]), "r"(b[1]));
}
__device__ __forceinline__ void sts128(uint32_t addr, uint4 v) {
    asm volatile("st.shared.v4.b32 [%0], {%1,%2,%3,%4};"
        :: "r"(addr), "r"(v.x), "r"(v.y), "r"(v.z), "r"(v.w) : "memory");
}

// ---------------- preprocessing ----------------
__global__ void k_wsplit(const float* __restrict__ W1, const int* __restrict__ ei) {
    if (blockIdx.x < 256) {
        int i = blockIdx.x * 256 + threadIdx.x;
        float f = W1[i];
        __nv_bfloat16 h = __float2bfloat16_rn(f);
        g_Whi[i] = h;
        g_Wlo[i] = __float2bfloat16_rn(f - __bfloat162float(h));
    } else if (blockIdx.x < 256 + NSB) {
        int i = (blockIdx.x - 256) * 256 + threadIdx.x;
        if (i < NN) g_p[0][i] = 1.0f;
    } else {
        int e = (blockIdx.x - 256 - NSB) * 256 + threadIdx.x;
        if (e < EE) atomicAdd(&g_deg[ei[EE + e]], 1);
    }
}

__global__ void __launch_bounds__(256) k_scan1() {
    __shared__ int sh[256];
    int t = threadIdx.x;
    int i = blockIdx.x * 256 + t;
    int v = 0;
    if (i < NN) {
        v = g_deg[i] + 1;          // +1 = self loop
        g_deg[i] = 0;              // reset for the next replay
        g_dinv[i] = rsqrtf((float)v);
    }
    sh[t] = v;
    __syncthreads();
#pragma unroll
    for (int off = 1; off < 256; off <<= 1) {
        int u = (t >= off) ? sh[t - off] : 0;
        __syncthreads();
        sh[t] += u;
        __syncthreads();
    }
    if (i < NN) g_rowptr[i] = sh[t] - v;
    if (t == 255) g_bsum[blockIdx.x] = sh[255];
}

__global__ void __launch_bounds__(256) k_scan3() {
    __shared__ int sh[256];
    int t = threadIdx.x;
    sh[t] = (t < NSB && t < (int)blockIdx.x) ? g_bsum[t] : 0;
    __syncthreads();
#pragma unroll
    for (int off = 128; off > 0; off >>= 1) {
        if (t < off) sh[t] += sh[t + off];
        __syncthreads();
    }
    int add = sh[0];
    int i = blockIdx.x * 256 + t;
    if (i < NN) { g_rowptr[i] += add; g_fill[i] = 0; }
    if (blockIdx.x == 0 && t == 0) g_rowptr[NN] = ET;
}

__global__ void k_fill(const int* __restrict__ ei) {
    int idx = blockIdx.x * blockDim.x + threadIdx.x;
    if (idx >= ET) return;
    int s, d;
    if (idx < EE) { s = ei[idx]; d = ei[EE + idx]; }
    else          { s = idx - EE; d = s; }
    int pos = g_rowptr[d] + atomicAdd(&g_fill[d], 1);
    float w = g_dinv[s] * g_dinv[d];
    g_cw[pos] = make_int2(s, __float_as_int(w));
}

// ---------------- GEMM1: BM=256 x BN=128 x BK=32, 16 warps (8x2), 32x64 tiles
__global__ void __launch_bounds__(512, 1) k_gemm1(const float* __restrict__ X,
                                                  const float* __restrict__ B1) {
    extern __shared__ __align__(16) char dsm[];
    uint32_t base = s2u(dsm);

    int tid = threadIdx.x;
    int wid = tid >> 5, lane = tid & 31;
    int warp_m = wid & 7;          // 8 row groups of 32
    int warp_n = wid >> 3;         // 2 col groups of 64
    int brow = blockIdx.x * 256;

    float acc[2][8][4];            // [mt 16-row][n8 tile][quad]
#pragma unroll
    for (int mt = 0; mt < 2; mt++)
#pragma unroll
        for (int nt = 0; nt < 8; nt++)
#pragma unroll
            for (int q = 0; q < 4; q++) acc[mt][nt][q] = 0.f;

    // A stage loads: row = tid>>1 (0..255), 16 floats at (tid&1)*16
    int lra = tid >> 1;
    int lca = (tid & 1) * 16;
    bool xok = (brow + lra) < NN;
    const float* xrow = X + (size_t)(brow + lra) * DIN + lca;
    uint32_t aoff = (uint32_t)(lra * LDP + lca) * 2;
    // W stage loads: row = tid>>2 (0..127), 8 elems at (tid&3)*8
    int lrw = tid >> 2;
    int lcw = (tid & 3) * 8;
    const __nv_bfloat16* whrow = g_Whi + (size_t)lrw * DIN + lcw;
    const __nv_bfloat16* wlrow = g_Wlo + (size_t)lrw * DIN + lcw;
    uint32_t woff = (uint32_t)(lrw * LDP + lcw) * 2;

    // ldmatrix lane addressing
    uint32_t a_r = warp_m * 32 + (lane & 15);
    uint32_t a_c = (lane >> 4) << 3;
    uint32_t b_r = warp_n * 64 + (lane & 7) + ((lane >> 4) << 3);
    uint32_t b_c = ((lane >> 3) & 1) << 3;

    float4 xf[4];
    uint4  whv, wlv;

    auto prefetch = [&](int s) {
        int k0 = s * 32;
        if (xok) {
            xf[0] = *(const float4*)(xrow + k0);
            xf[1] = *(const float4*)(xrow + k0 + 4);
            xf[2] = *(const float4*)(xrow + k0 + 8);
            xf[3] = *(const float4*)(xrow + k0 + 12);
        } else {
            xf[0] = xf[1] = xf[2] = xf[3] = make_float4(0.f, 0.f, 0.f, 0.f);
        }
        whv = *(const uint4*)(whrow + k0);
        wlv = *(const uint4*)(wlrow + k0);
    };
    auto cvstore = [&](int buf) {
        uint32_t tAh = base + buf * BUF_B;
        uint32_t tAl = tAh + A_TILE;
        uint32_t tBh = tAl + A_TILE;
        uint32_t tBl = tBh + B_TILE;
#pragma unroll
        for (int q = 0; q < 2; q++) {
            float4 f0 = xf[q * 2], f1 = xf[q * 2 + 1];
            __nv_bfloat162 h01 = __floats2bfloat162_rn(f0.x, f0.y);
            __nv_bfloat162 h23 = __floats2bfloat162_rn(f0.z, f0.w);
            __nv_bfloat162 h45 = __floats2bfloat162_rn(f1.x, f1.y);
            __nv_bfloat162 h67 = __floats2bfloat162_rn(f1.z, f1.w);
            float2 r01 = __bfloat1622float2(h01), r23 = __bfloat1622float2(h23);
            float2 r45 = __bfloat1622float2(h45), r67 = __bfloat1622float2(h67);
            sts128(tAh + aoff + q * 16,
                   make_uint4(b2u(h01), b2u(h23), b2u(h45), b2u(h67)));
            sts128(tAl + aoff + q * 16, make_uint4(
                b2u(__floats2bfloat162_rn(f0.x - r01.x, f0.y - r01.y)),
                b2u(__floats2bfloat162_rn(f0.z - r23.x, f0.w - r23.y)),
                b2u(__floats2bfloat162_rn(f1.x - r45.x, f1.y - r45.y)),
                b2u(__floats2bfloat162_rn(f1.z - r67.x, f1.w - r67.y))));
        }
        sts128(tBh + woff, whv);
        sts128(tBl + woff, wlv);
    };

    prefetch(0);
    cvstore(0);
    __syncthreads();

    for (int s = 0; s < DIN / 32; s++) {          // 16 stages
        if (s + 1 < DIN / 32) prefetch(s + 1);

        int buf = s & 1;
        uint32_t tAh = base + buf * BUF_B;
        uint32_t tAl = tAh + A_TILE;
        uint32_t tBh = tAl + A_TILE;
        uint32_t tBl = tBh + B_TILE;
#pragma unroll
        for (int ks = 0; ks < 32; ks += 16) {
            unsigned Ah[2][4], Al[2][4];
#pragma unroll
            for (int mt = 0; mt < 2; mt++) {
                uint32_t off = ((a_r + mt * 16) * LDP + ks + a_c) * 2;
                ldsm4(Ah[mt], tAh + off);
                ldsm4(Al[mt], tAl + off);
            }
#pragma unroll
            for (int ntp = 0; ntp < 4; ntp++) {
                unsigned Bh[4], Bl[4];
                uint32_t off = ((b_r + ntp * 16) * LDP + ks + b_c) * 2;
                ldsm4(Bh, tBh + off);
                ldsm4(Bl, tBl + off);
#pragma unroll
                for (int mt = 0; mt < 2; mt++) {
                    mma16816(acc[mt][ntp * 2],     Ah[mt], &Bh[0]);
                    mma16816(acc[mt][ntp * 2],     Ah[mt], &Bl[0]);
                    mma16816(acc[mt][ntp * 2],     Al[mt], &Bh[0]);
                    mma16816(acc[mt][ntp * 2 + 1], Ah[mt], &Bh[2]);
                    mma16816(acc[mt][ntp * 2 + 1], Ah[mt], &Bl[2]);
                    mma16816(acc[mt][ntp * 2 + 1], Al[mt], &Bh[2]);
                }
            }
        }

        if (s + 1 < DIN / 32) {
            cvstore((s + 1) & 1);
            __syncthreads();
        }
    }

    // epilogue: bias + relu; write g_hb[0] (iterate) and g_hb[2] (h0), fp16
    int group = lane >> 2, tig = lane & 3;
#pragma unroll
    for (int mt = 0; mt < 2; mt++) {
#pragma unroll
        for (int nt = 0; nt < 8; nt++) {
            int col = warp_n * 64 + nt * 8 + 2 * tig;
            float bx = B1[col], by = B1[col + 1];
#pragma unroll
            for (int h = 0; h < 2; h++) {
                int row = brow + warp_m * 32 + mt * 16 + group + h * 8;
                if (row >= NN) continue;
                float v0 = fmaxf(acc[mt][nt][h * 2]     + bx, 0.f);
                float v1 = fmaxf(acc[mt][nt][h * 2 + 1] + by, 0.f);
                __half2 hv = __floats2half2_rn(v0, v1);
                size_t off = ((size_t)row << 6) + (col >> 1);
                g_hb[0][off] = hv;
                g_hb[2][off] = hv;
            }
        }
    }
}

// ---------------- fused APPNP step (gather + spread copy) --------------------
__device__ __forceinline__ void acc_edge(const __half2* __restrict__ xin,
                                         int s, float w, int lane,
                                         float& a0, float& a1, float& a2, float& a3) {
    uint2 raw = __ldg((const uint2*)(xin + ((size_t)s << 6) + (lane << 1)));
    float2 f01 = __half22float2(*reinterpret_cast<__half2*>(&raw.x));
    float2 f23 = __half22float2(*reinterpret_cast<__half2*>(&raw.y));
    a0 += w * f01.x; a1 += w * f01.y; a2 += w * f23.x; a3 += w * f23.y;
}

__global__ void __launch_bounds__(256) k_diff(int inb, int outb, int pin_i, int pout_i,
                                              float* __restrict__ emb_out, int last,
                                              int it,
                                              const float4* __restrict__ csrc,
                                              float4* __restrict__ cdst) {
    if (blockIdx.x < NBF2) {
        int wg   = (blockIdx.x << 3) + (threadIdx.x >> 5);
        int lane = threadIdx.x & 31;
        int n0 = wg << 3;
        int n1 = n0 + 8; if (n1 > NN) n1 = NN;
        const __half2* __restrict__ xin = g_hb[inb];
        for (int n = n0; n < n1; n++) {
            int beg = g_rowptr[n], end = g_rowptr[n + 1];
            float a0 = 0.f, a1 = 0.f, a2 = 0.f, a3 = 0.f;
            int e = beg;
            if ((e & 1) && e < end) {
                int2 cw = __ldg(&g_cw[e]);
                acc_edge(xin, cw.x, __int_as_float(cw.y), lane, a0, a1, a2, a3);
                e++;
            }
            for (; e + 8 <= end; e += 8) {
                int4 q0 = __ldg((const int4*)(g_cw + e));
                int4 q1 = __ldg((const int4*)(g_cw + e + 2));
                int4 q2 = __ldg((const int4*)(g_cw + e + 4));
                int4 q3 = __ldg((const int4*)(g_cw + e + 6));
                uint2 v[8];
                v[0] = __ldg((const uint2*)(xin + ((size_t)q0.x << 6) + (lane << 1)));
                v[1] = __ldg((const uint2*)(xin + ((size_t)q0.z << 6) + (lane << 1)));
                v[2] = __ldg((const uint2*)(xin + ((size_t)q1.x << 6) + (lane << 1)));
                v[3] = __ldg((const uint2*)(xin + ((size_t)q1.z << 6) + (lane << 1)));
                v[4] = __ldg((const uint2*)(xin + ((size_t)q2.x << 6) + (lane << 1)));
                v[5] = __ldg((const uint2*)(xin + ((size_t)q2.z << 6) + (lane << 1)));
                v[6] = __ldg((const uint2*)(xin + ((size_t)q3.x << 6) + (lane << 1)));
                v[7] = __ldg((const uint2*)(xin + ((size_t)q3.z << 6) + (lane << 1)));
                float wv[8] = {__int_as_float(q0.y), __int_as_float(q0.w),
                               __int_as_float(q1.y), __int_as_float(q1.w),
                               __int_as_float(q2.y), __int_as_float(q2.w),
                               __int_as_float(q3.y), __int_as_float(q3.w)};
#pragma unroll
                for (int i = 0; i < 8; i++) {
                    float2 f01 = __half22float2(*reinterpret_cast<__half2*>(&v[i].x));
                    float2 f23 = __half22float2(*reinterpret_cast<__half2*>(&v[i].y));
                    a0 += wv[i] * f01.x; a1 += wv[i] * f01.y;
                    a2 += wv[i] * f23.x; a3 += wv[i] * f23.y;
                }
            }
            for (; e + 2 <= end; e += 2) {
                int4 q = __ldg((const int4*)(g_cw + e));
                acc_edge(xin, q.x, __int_as_float(q.y), lane, a0, a1, a2, a3);
                acc_edge(xin, q.z, __int_as_float(q.w), lane, a0, a1, a2, a3);
            }
            if (e < end) {
                int2 cw = __ldg(&g_cw[e]);
                acc_edge(xin, cw.x, __int_as_float(cw.y), lane, a0, a1, a2, a3);
            }
            uint2 hraw = __ldg((const uint2*)(g_hb[2] + ((size_t)n << 6) + (lane << 1)));
            float2 h01 = __half22float2(*reinterpret_cast<__half2*>(&hraw.x));
            float2 h23 = __half22float2(*reinterpret_cast<__half2*>(&hraw.y));
            float4 o = make_float4(OMA * a0 + AL * h01.x, OMA * a1 + AL * h01.y,
                                   OMA * a2 + AL * h23.x, OMA * a3 + AL * h23.y);
            if (last) {
                *(float4*)(emb_out + ((size_t)n << 7) + (lane << 2)) = o;
            } else {
                uint2 hp;
                hp.x = h2u(__floats2half2_rn(o.x, o.y));
                hp.y = h2u(__floats2half2_rn(o.z, o.w));
                *(uint2*)(&g_hb[outb][((size_t)n << 6) + (lane << 1)]) = hp;
            }
        }
    } else if (blockIdx.x < NBF2 + NBP) {
        int v = (blockIdx.x - NBF2) * 256 + threadIdx.x;
        if (v >= NN) return;
        const float* __restrict__ pin = g_p[pin_i];
        float acc = 0.f;
        int beg = g_rowptr[v], end = g_rowptr[v + 1];
        int e = beg;
        if ((e & 1) && e < end) {
            int2 cw = __ldg(&g_cw[e]);
            acc += __int_as_float(cw.y) * __ldg(&pin[cw.x]);
            e++;
        }
        for (; e + 4 <= end; e += 4) {
            int4 q0 = __ldg((const int4*)(g_cw + e));
            int4 q1 = __ldg((const int4*)(g_cw + e + 2));
            float p0 = __ldg(&pin[q0.x]), p1 = __ldg(&pin[q0.z]);
            float p2 = __ldg(&pin[q1.x]), p3 = __ldg(&pin[q1.z]);
            acc += __int_as_float(q0.y) * p0 + __int_as_float(q0.w) * p1
                 + __int_as_float(q1.y) * p2 + __int_as_float(q1.w) * p3;
        }
        for (; e < end; e++) {
            int2 cw = __ldg(&g_cw[e]);
            acc += __int_as_float(cw.y) * __ldg(&pin[cw.x]);
        }
        g_p[pout_i][v] = OMA * acc + AL;
    } else {
        // x-passthrough copy, 1/10th per iteration: CPIT blocks x 2048 float4
        int b = it * CPIT + (blockIdx.x - NBF2 - NBP);
        int i = b * 2048 + threadIdx.x;
#pragma unroll
        for (int r = 0; r < 8; r++) {
            int idx = i + r * 256;
            if (idx < NN * DIN / 4) cdst[idx] = csrc[idx];
        }
    }
}

// ---------------- GEMM2: out = emb1 @ W2^T + p * b2^T ----------------
__global__ void __launch_bounds__(256) k_gemm2(const float* __restrict__ EMB,
                                               const float* __restrict__ W2,
                                               const float* __restrict__ B2,
                                               float* __restrict__ out) {
    __shared__ float wst[DH][DC + 4];
    __shared__ float xs[16][DH];
    int tid = threadIdx.x;
#pragma unroll
    for (int i = 0; i < 8; i++) {
        int slot = tid + i * 256;
        int j = slot >> 5, k4 = slot & 31;
        float4 v = *(const float4*)(W2 + (size_t)j * DH + k4 * 4);
        wst[k4 * 4 + 0][j] = v.x; wst[k4 * 4 + 1][j] = v.y;
        wst[k4 * 4 + 2][j] = v.z; wst[k4 * 4 + 3][j] = v.w;
    }
    int n0 = blockIdx.x * 16;
#pragma unroll
    for (int i = 0; i < 2; i++) {
        int slot = tid + i * 256;
        int r = slot >> 5, k4 = slot & 31;
        int gn = n0 + r;
        float4 v = (gn < NN) ? *(const float4*)(EMB + (size_t)gn * DH + k4 * 4)
                             : make_float4(0.f, 0.f, 0.f, 0.f);
        *(float4*)&xs[r][k4 * 4] = v;
    }
    __syncthreads();
    int nl = tid >> 4, jg = tid & 15;
    float a0 = 0.f, a1 = 0.f, a2 = 0.f, a3 = 0.f;
#pragma unroll
    for (int k = 0; k < DH; k++) {
        float xv = xs[nl][k];
        float4 wv = *(const float4*)&wst[k][jg * 4];
        a0 += xv * wv.x; a1 += xv * wv.y; a2 += xv * wv.z; a3 += xv * wv.w;
    }
    int gn = n0 + nl;
    if (gn < NN) {
        float pv = g_p[0][gn];
        float4 bv = *(const float4*)(B2 + jg * 4);
        float4 o = make_float4(a0 + pv * bv.x, a1 + pv * bv.y,
                               a2 + pv * bv.z, a3 + pv * bv.w);
        *(float4*)(out + (size_t)gn * DC + jg * 4) = o;
    }
}

// ---------------- host launcher ----------------
extern "C" void kernel_launch(void* const* d_in, const int* in_sizes, int n_in,
                              void* d_out, int out_size) {
    const float* X  = (const float*)d_in[0];
    const int*   EI = (const int*)  d_in[1];
    const float* W1 = (const float*)d_in[2];
    const float* B1 = (const float*)d_in[3];
    const float* W2 = (const float*)d_in[4];
    const float* B2 = (const float*)d_in[5];
    float* out = (float*)d_out;
    float* emb_out = out + (size_t)NN * DIN;
    float* cls_out = out + (size_t)NN * (DIN + DH);

    cudaFuncSetAttribute(k_gemm1, cudaFuncAttributeMaxDynamicSharedMemorySize, G1_SMEM);

    // ordered so the profiler slot (4th launch) = k_gemm1
    k_wsplit<<<256 + NSB + DEGB, 256>>>(W1, EI);   // W split + p init + deg
    k_scan1 <<<NSB, 256>>>();                      // scan + dinv + deg reset
    k_scan3 <<<NSB, 256>>>();                      // offsets + fill reset
    k_gemm1 <<<G1B, 512, G1_SMEM>>>(X, B1);
    k_fill  <<<(ET + 255) / 256, 256>>>(EI);

    // fused APPNP: fp16 features (ping-pong 0<->1, h0 in hb2) + p + 1/10 copy
    {
        int pin = 0, pob = 1;
        for (int it = 0; it < KIT; it++) {
            int last = (it == KIT - 1);
            k_diff<<<NBF2 + NBP + CPIT, 256>>>(it & 1, (it + 1) & 1, pin, pob,
                                               emb_out, last, it,
                                               (const float4*)X, (float4*)out);
            int t = pin; pin = pob; pob = t;
        }
    }

    k_gemm2<<<(NN + 15) / 16, 256>>>(emb_out, W2, B2, cls_out);
}

// round 14
// speedup vs baseline: 1.0329x; 1.0329x over previous
#include <cuda_runtime.h>
#include <cuda_fp16.h>
#include <cuda_bf16.h>
#include <cstdint>

#define NN   50000
#define EE   800000
#define ET   (EE + NN)
#define DIN  512
#define DH   128
#define DC   64
#define KIT  10
#define AL   0.1f
#define OMA  0.9f

#define NBF2 ((NN + 63) / 64)      // feature-diffusion blocks (8 warps x 8 nodes)
#define NBP  ((NN + 255) / 256)    // p-diffusion blocks
#define NSB  ((NN + 255) / 256)    // scan blocks (196)
#define G1B  ((NN + 127) / 128)    // gemm1 tiles (391)
#define CPIT 313                   // copy blocks per diffusion iteration

#define LDP    40                  // padded smem row (elements); 80B rows
#define TILE_B (128 * LDP * 2)     // bytes per smem tile (10240)
#define G1_SMEM (8 * TILE_B)       // 2 bufs x {Ah,Al,Bh,Bl} = 81920

typedef unsigned long long u64;

// ---------------- device scratch ----------------
__device__ int     g_deg[NN];
__device__ float   g_dinv[NN];
__device__ int     g_rowptr[NN + 1];
__device__ int     g_fill[NN];
__device__ __align__(16) int2 g_cw[ET];
__device__ int     g_bsum[256];
__device__ __align__(16) __nv_bfloat16 g_Whi[DH * DIN];
__device__ __align__(16) __nv_bfloat16 g_Wlo[DH * DIN];
// 0/1 = ping-pong iterates, 2 = h0 (h1 after relu), all fp16
__device__ __half2 g_hb[3][(size_t)NN * (DH/2)];
__device__ float   g_p[2][NN];

// ---------------- helpers ----------------
__device__ __forceinline__ uint32_t s2u(const void* p) {
    uint32_t a;
    asm("{ .reg .u64 t; cvta.to.shared.u64 t, %1; cvt.u32.u64 %0, t; }" : "=r"(a) : "l"(p));
    return a;
}
__device__ __forceinline__ unsigned h2u(__half2 h) {
    unsigned u; *reinterpret_cast<__half2*>(&u) = h; return u;
}
__device__ __forceinline__ unsigned b2u(__nv_bfloat162 h) {
    unsigned u; *reinterpret_cast<__nv_bfloat162*>(&u) = h; return u;
}
__device__ __forceinline__ void ldsm4(unsigned* r, uint32_t addr) {
    asm volatile("ldmatrix.sync.aligned.m8n8.x4.shared.b16 {%0,%1,%2,%3}, [%4];"
        : "=r"(r[0]), "=r"(r[1]), "=r"(r[2]), "=r"(r[3]) : "r"(addr));
}
__device__ __forceinline__ void mma16816(float* c, const unsigned* a, const unsigned* b) {
    asm volatile("mma.sync.aligned.m16n8k16.row.col.f32.bf16.bf16.f32 "
        "{%0,%1,%2,%3}, {%4,%5,%6,%7}, {%8,%9}, {%0,%1,%2,%3};"
        : "+f"(c[0]), "+f"(c[1]), "+f"(c[2]), "+f"(c[3])
        : "r"(a[0]), "r"(a[1]), "r"(a[2]), "r"(a[3]), "r"(b[0]), "r"(b[1]));
}
__device__ __forceinline__ void sts128(uint32_t addr, uint4 v) {
    asm volatile("st.shared.v4.b32 [%0], {%1,%2,%3,%4};"
        :: "r"(addr), "r"(v.x), "r"(v.y), "r"(v.z), "r"(v.w) : "memory");
}

// ---------------- preprocessing ----------------
__global__ void k_wsplit(const float* __restrict__ W1) {
    if (blockIdx.x < 256) {
        int i = blockIdx.x * 256 + threadIdx.x;
        float f = W1[i];
        __nv_bfloat16 h = __float2bfloat16_rn(f);
        g_Whi[i] = h;
        g_Wlo[i] = __float2bfloat16_rn(f - __bfloat162float(h));
    } else {
        int i = (blockIdx.x - 256) * 256 + threadIdx.x;
        if (i < NN) { g_deg[i] = 1; g_fill[i] = 0; g_p[0][i] = 1.0f; }
    }
}

__global__ void k_deg(const int* __restrict__ ei) {
    int e = blockIdx.x * blockDim.x + threadIdx.x;
    if (e < EE) atomicAdd(&g_deg[ei[EE + e]], 1);
}

__global__ void __launch_bounds__(256) k_scan1() {
    __shared__ int sh[256];
    int t = threadIdx.x;
    int i = blockIdx.x * 256 + t;
    int v = (i < NN) ? g_deg[i] : 0;
    if (i < NN) g_dinv[i] = rsqrtf((float)v);
    sh[t] = v;
    __syncthreads();
#pragma unroll
    for (int off = 1; off < 256; off <<= 1) {
        int u = (t >= off) ? sh[t - off] : 0;
        __syncthreads();
        sh[t] += u;
        __syncthreads();
    }
    if (i < NN) g_rowptr[i] = sh[t] - v;
    if (t == 255) g_bsum[blockIdx.x] = sh[255];
}

// fused scan2+scan3: each block reduces the block sums below it locally
__global__ void __launch_bounds__(256) k_scan3() {
    __shared__ int sh[256];
    int t = threadIdx.x;
    sh[t] = (t < NSB && t < (int)blockIdx.x) ? g_bsum[t] : 0;
    __syncthreads();
#pragma unroll
    for (int off = 128; off > 0; off >>= 1) {
        if (t < off) sh[t] += sh[t + off];
        __syncthreads();
    }
    int add = sh[0];
    int i = blockIdx.x * 256 + t;
    if (i < NN) g_rowptr[i] += add;
    if (blockIdx.x == 0 && t == 0) g_rowptr[NN] = ET;
}

__global__ void k_fill(const int* __restrict__ ei) {
    int idx = blockIdx.x * blockDim.x + threadIdx.x;
    if (idx >= ET) return;
    int s, d;
    if (idx < EE) { s = ei[idx]; d = ei[EE + idx]; }
    else          { s = idx - EE; d = s; }
    int pos = g_rowptr[d] + atomicAdd(&g_fill[d], 1);
    float w = g_dinv[s] * g_dinv[d];
    g_cw[pos] = make_int2(s, __float_as_int(w));
}

// ---------------- GEMM1: 512-thread pipelined HMMA (BM=128) ------------------
__global__ void __launch_bounds__(512, 1) k_gemm1(const float* __restrict__ X,
                                                  const float* __restrict__ B1) {
    extern __shared__ __align__(16) char dsm[];
    uint32_t base = s2u(dsm);

    int tid = threadIdx.x;
    int wid = tid >> 5, lane = tid & 31;
    int warp_m = wid & 3, warp_n = wid >> 2;
    int brow = blockIdx.x * 128;

    float acc[2][4][4];
#pragma unroll
    for (int mt = 0; mt < 2; mt++)
#pragma unroll
        for (int nt = 0; nt < 4; nt++)
#pragma unroll
            for (int q = 0; q < 4; q++) acc[mt][nt][q] = 0.f;

    int lrow = tid >> 2;
    int lc   = (tid & 3) * 8;
    bool xok = (brow + lrow) < NN;
    const float* xrow = X + (size_t)(brow + lrow) * DIN + lc;
    const __nv_bfloat16* whrow = g_Whi + (size_t)lrow * DIN + lc;
    const __nv_bfloat16* wlrow = g_Wlo + (size_t)lrow * DIN + lc;
    uint32_t aoff = (uint32_t)(lrow * LDP + lc) * 2;

    uint32_t a_r = warp_m * 32 + (lane & 15);
    uint32_t a_c = (lane >> 4) << 3;
    uint32_t b_r = warp_n * 32 + (lane & 7) + ((lane >> 4) << 3);
    uint32_t b_c = ((lane >> 3) & 1) << 3;

    float4 xf[2];
    uint4  whv, wlv;

    auto prefetch = [&](int s) {
        int k0 = s * 32;
        if (xok) {
            xf[0] = *(const float4*)(xrow + k0);
            xf[1] = *(const float4*)(xrow + k0 + 4);
        } else {
            xf[0] = xf[1] = make_float4(0.f, 0.f, 0.f, 0.f);
        }
        whv = *(const uint4*)(whrow + k0);
        wlv = *(const uint4*)(wlrow + k0);
    };
    auto cvstore = [&](int buf) {
        uint32_t tAh = base + (buf * 4 + 0) * TILE_B;
        uint32_t tAl = base + (buf * 4 + 1) * TILE_B;
        uint32_t tBh = base + (buf * 4 + 2) * TILE_B;
        uint32_t tBl = base + (buf * 4 + 3) * TILE_B;
        float4 f0 = xf[0], f1 = xf[1];
        __nv_bfloat162 h01 = __floats2bfloat162_rn(f0.x, f0.y);
        __nv_bfloat162 h23 = __floats2bfloat162_rn(f0.z, f0.w);
        __nv_bfloat162 h45 = __floats2bfloat162_rn(f1.x, f1.y);
        __nv_bfloat162 h67 = __floats2bfloat162_rn(f1.z, f1.w);
        float2 r01 = __bfloat1622float2(h01), r23 = __bfloat1622float2(h23);
        float2 r45 = __bfloat1622float2(h45), r67 = __bfloat1622float2(h67);
        sts128(tAh + aoff, make_uint4(b2u(h01), b2u(h23), b2u(h45), b2u(h67)));
        sts128(tAl + aoff, make_uint4(
            b2u(__floats2bfloat162_rn(f0.x - r01.x, f0.y - r01.y)),
            b2u(__floats2bfloat162_rn(f0.z - r23.x, f0.w - r23.y)),
            b2u(__floats2bfloat162_rn(f1.x - r45.x, f1.y - r45.y)),
            b2u(__floats2bfloat162_rn(f1.z - r67.x, f1.w - r67.y))));
        sts128(tBh + aoff, whv);
        sts128(tBl + aoff, wlv);
    };

    prefetch(0);
    cvstore(0);
    __syncthreads();

    for (int s = 0; s < DIN / 32; s++) {          // 16 stages
        if (s + 1 < DIN / 32) prefetch(s + 1);

        int buf = s & 1;
        uint32_t tAh = base + (buf * 4 + 0) * TILE_B;
        uint32_t tAl = base + (buf * 4 + 1) * TILE_B;
        uint32_t tBh = base + (buf * 4 + 2) * TILE_B;
        uint32_t tBl = base + (buf * 4 + 3) * TILE_B;
#pragma unroll
        for (int ks = 0; ks < 32; ks += 16) {
            unsigned Ah[2][4], Al[2][4];
#pragma unroll
            for (int mt = 0; mt < 2; mt++) {
                uint32_t off = ((a_r + mt * 16) * LDP + ks + a_c) * 2;
                ldsm4(Ah[mt], tAh + off);
                ldsm4(Al[mt], tAl + off);
            }
#pragma unroll
            for (int ntp = 0; ntp < 2; ntp++) {
                unsigned Bh[4], Bl[4];
                uint32_t off = ((b_r + ntp * 16) * LDP + ks + b_c) * 2;
                ldsm4(Bh, tBh + off);
                ldsm4(Bl, tBl + off);
#pragma unroll
                for (int mt = 0; mt < 2; mt++) {
                    mma16816(acc[mt][ntp * 2],     Ah[mt], &Bh[0]);
                    mma16816(acc[mt][ntp * 2],     Ah[mt], &Bl[0]);
                    mma16816(acc[mt][ntp * 2],     Al[mt], &Bh[0]);
                    mma16816(acc[mt][ntp * 2 + 1], Ah[mt], &Bh[2]);
                    mma16816(acc[mt][ntp * 2 + 1], Ah[mt], &Bl[2]);
                    mma16816(acc[mt][ntp * 2 + 1], Al[mt], &Bh[2]);
                }
            }
        }

        if (s + 1 < DIN / 32) {
            cvstore((s + 1) & 1);
            __syncthreads();
        }
    }

    int group = lane >> 2, tig = lane & 3;
#pragma unroll
    for (int mt = 0; mt < 2; mt++) {
#pragma unroll
        for (int nt = 0; nt < 4; nt++) {
            int col = warp_n * 32 + nt * 8 + 2 * tig;
            float bx = B1[col], by = B1[col + 1];
#pragma unroll
            for (int h = 0; h < 2; h++) {
                int row = brow + warp_m * 32 + mt * 16 + group + h * 8;
                if (row >= NN) continue;
                float v0 = fmaxf(acc[mt][nt][h * 2]     + bx, 0.f);
                float v1 = fmaxf(acc[mt][nt][h * 2 + 1] + by, 0.f);
                __half2 hv = __floats2half2_rn(v0, v1);
                size_t off = ((size_t)row << 6) + (col >> 1);
                g_hb[0][off] = hv;
                g_hb[2][off] = hv;
            }
        }
    }
}

// ---------------- fused APPNP step (gather + spread copy) --------------------
__device__ __forceinline__ void acc_edge(const __half2* __restrict__ xin,
                                         int s, float w, int lane,
                                         float& a0, float& a1, float& a2, float& a3) {
    uint2 raw = __ldg((const uint2*)(xin + ((size_t)s << 6) + (lane << 1)));
    float2 f01 = __half22float2(*reinterpret_cast<__half2*>(&raw.x));
    float2 f23 = __half22float2(*reinterpret_cast<__half2*>(&raw.y));
    a0 += w * f01.x; a1 += w * f01.y; a2 += w * f23.x; a3 += w * f23.y;
}

__global__ void __launch_bounds__(256) k_diff(int inb, int outb, int pin_i, int pout_i,
                                              float* __restrict__ emb_out, int last,
                                              int it,
                                              const float4* __restrict__ csrc,
                                              float4* __restrict__ cdst) {
    if (blockIdx.x < NBF2) {
        int wg   = (blockIdx.x << 3) + (threadIdx.x >> 5);
        int lane = threadIdx.x & 31;
        int n0 = wg << 3;
        int n1 = n0 + 8; if (n1 > NN) n1 = NN;
        const __half2* __restrict__ xin = g_hb[inb];
        for (int n = n0; n < n1; n++) {
            int beg = g_rowptr[n], end = g_rowptr[n + 1];
            float a0 = 0.f, a1 = 0.f, a2 = 0.f, a3 = 0.f;
            int e = beg;
            if ((e & 1) && e < end) {
                int2 cw = __ldg(&g_cw[e]);
                acc_edge(xin, cw.x, __int_as_float(cw.y), lane, a0, a1, a2, a3);
                e++;
            }
            for (; e + 8 <= end; e += 8) {
                int4 q0 = __ldg((const int4*)(g_cw + e));
                int4 q1 = __ldg((const int4*)(g_cw + e + 2));
                int4 q2 = __ldg((const int4*)(g_cw + e + 4));
                int4 q3 = __ldg((const int4*)(g_cw + e + 6));
                uint2 v[8];
                v[0] = __ldg((const uint2*)(xin + ((size_t)q0.x << 6) + (lane << 1)));
                v[1] = __ldg((const uint2*)(xin + ((size_t)q0.z << 6) + (lane << 1)));
                v[2] = __ldg((const uint2*)(xin + ((size_t)q1.x << 6) + (lane << 1)));
                v[3] = __ldg((const uint2*)(xin + ((size_t)q1.z << 6) + (lane << 1)));
                v[4] = __ldg((const uint2*)(xin + ((size_t)q2.x << 6) + (lane << 1)));
                v[5] = __ldg((const uint2*)(xin + ((size_t)q2.z << 6) + (lane << 1)));
                v[6] = __ldg((const uint2*)(xin + ((size_t)q3.x << 6) + (lane << 1)));
                v[7] = __ldg((const uint2*)(xin + ((size_t)q3.z << 6) + (lane << 1)));
                float wv[8] = {__int_as_float(q0.y), __int_as_float(q0.w),
                               __int_as_float(q1.y), __int_as_float(q1.w),
                               __int_as_float(q2.y), __int_as_float(q2.w),
                               __int_as_float(q3.y), __int_as_float(q3.w)};
#pragma unroll
                for (int i = 0; i < 8; i++) {
                    float2 f01 = __half22float2(*reinterpret_cast<__half2*>(&v[i].x));
                    float2 f23 = __half22float2(*reinterpret_cast<__half2*>(&v[i].y));
                    a0 += wv[i] * f01.x; a1 += wv[i] * f01.y;
                    a2 += wv[i] * f23.x; a3 += wv[i] * f23.y;
                }
            }
            for (; e + 2 <= end; e += 2) {
                int4 q = __ldg((const int4*)(g_cw + e));
                acc_edge(xin, q.x, __int_as_float(q.y), lane, a0, a1, a2, a3);
                acc_edge(xin, q.z, __int_as_float(q.w), lane, a0, a1, a2, a3);
            }
            if (e < end) {
                int2 cw = __ldg(&g_cw[e]);
                acc_edge(xin, cw.x, __int_as_float(cw.y), lane, a0, a1, a2, a3);
            }
            uint2 hraw = __ldg((const uint2*)(g_hb[2] + ((size_t)n << 6) + (lane << 1)));
            float2 h01 = __half22float2(*reinterpret_cast<__half2*>(&hraw.x));
            float2 h23 = __half22float2(*reinterpret_cast<__half2*>(&hraw.y));
            float4 o = make_float4(OMA * a0 + AL * h01.x, OMA * a1 + AL * h01.y,
                                   OMA * a2 + AL * h23.x, OMA * a3 + AL * h23.y);
            if (last) {
                *(float4*)(emb_out + ((size_t)n << 7) + (lane << 2)) = o;
            } else {
                uint2 hp;
                hp.x = h2u(__floats2half2_rn(o.x, o.y));
                hp.y = h2u(__floats2half2_rn(o.z, o.w));
                *(uint2*)(&g_hb[outb][((size_t)n << 6) + (lane << 1)]) = hp;
            }
        }
    } else if (blockIdx.x < NBF2 + NBP) {
        int v = (blockIdx.x - NBF2) * 256 + threadIdx.x;
        if (v >= NN) return;
        const float* __restrict__ pin = g_p[pin_i];
        float acc = 0.f;
        int beg = g_rowptr[v], end = g_rowptr[v + 1];
        int e = beg;
        if ((e & 1) && e < end) {
            int2 cw = __ldg(&g_cw[e]);
            acc += __int_as_float(cw.y) * __ldg(&pin[cw.x]);
            e++;
        }
        for (; e + 4 <= end; e += 4) {
            int4 q0 = __ldg((const int4*)(g_cw + e));
            int4 q1 = __ldg((const int4*)(g_cw + e + 2));
            float p0 = __ldg(&pin[q0.x]), p1 = __ldg(&pin[q0.z]);
            float p2 = __ldg(&pin[q1.x]), p3 = __ldg(&pin[q1.z]);
            acc += __int_as_float(q0.y) * p0 + __int_as_float(q0.w) * p1
                 + __int_as_float(q1.y) * p2 + __int_as_float(q1.w) * p3;
        }
        for (; e < end; e++) {
            int2 cw = __ldg(&g_cw[e]);
            acc += __int_as_float(cw.y) * __ldg(&pin[cw.x]);
        }
        g_p[pout_i][v] = OMA * acc + AL;
    } else {
        // x-passthrough copy, 1/10th per iteration: CPIT blocks x 2048 float4
        int b = it * CPIT + (blockIdx.x - NBF2 - NBP);
        int i = b * 2048 + threadIdx.x;
#pragma unroll
        for (int r = 0; r < 8; r++) {
            int idx = i + r * 256;
            if (idx < NN * DIN / 4) cdst[idx] = csrc[idx];
        }
    }
}

// ---------------- GEMM2: out = emb1 @ W2^T + p * b2^T ----------------
__global__ void __launch_bounds__(256) k_gemm2(const float* __restrict__ EMB,
                                               const float* __restrict__ W2,
                                               const float* __restrict__ B2,
                                               float* __restrict__ out) {
    __shared__ float wst[DH][DC + 4];
    __shared__ float xs[16][DH];
    int tid = threadIdx.x;
#pragma unroll
    for (int i = 0; i < 8; i++) {
        int slot = tid + i * 256;
        int j = slot >> 5, k4 = slot & 31;
        float4 v = *(const float4*)(W2 + (size_t)j * DH + k4 * 4);
        wst[k4 * 4 + 0][j] = v.x; wst[k4 * 4 + 1][j] = v.y;
        wst[k4 * 4 + 2][j] = v.z; wst[k4 * 4 + 3][j] = v.w;
    }
    int n0 = blockIdx.x * 16;
#pragma unroll
    for (int i = 0; i < 2; i++) {
        int slot = tid + i * 256;
        int r = slot >> 5, k4 = slot & 31;
        int gn = n0 + r;
        float4 v = (gn < NN) ? *(const float4*)(EMB + (size_t)gn * DH + k4 * 4)
                             : make_float4(0.f, 0.f, 0.f, 0.f);
        *(float4*)&xs[r][k4 * 4] = v;
    }
    __syncthreads();
    int nl = tid >> 4, jg = tid & 15;
    float a0 = 0.f, a1 = 0.f, a2 = 0.f, a3 = 0.f;
#pragma unroll
    for (int k = 0; k < DH; k++) {
        float xv = xs[nl][k];
        float4 wv = *(const float4*)&wst[k][jg * 4];
        a0 += xv * wv.x; a1 += xv * wv.y; a2 += xv * wv.z; a3 += xv * wv.w;
    }
    int gn = n0 + nl;
    if (gn < NN) {
        float pv = g_p[0][gn];
        float4 bv = *(const float4*)(B2 + jg * 4);
        float4 o = make_float4(a0 + pv * bv.x, a1 + pv * bv.y,
                               a2 + pv * bv.z, a3 + pv * bv.w);
        *(float4*)(out + (size_t)gn * DC + jg * 4) = o;
    }
}

// ---------------- host launcher ----------------
extern "C" void kernel_launch(void* const* d_in, const int* in_sizes, int n_in,
                              void* d_out, int out_size) {
    const float* X  = (const float*)d_in[0];
    const int*   EI = (const int*)  d_in[1];
    const float* W1 = (const float*)d_in[2];
    const float* B1 = (const float*)d_in[3];
    const float* W2 = (const float*)d_in[4];
    const float* B2 = (const float*)d_in[5];
    float* out = (float*)d_out;
    float* emb_out = out + (size_t)NN * DIN;
    float* cls_out = out + (size_t)NN * (DIN + DH);

    cudaFuncSetAttribute(k_gemm1, cudaFuncAttributeMaxDynamicSharedMemorySize, G1_SMEM);

    // ordered so the profiler slot (4th launch) = k_gemm1
    k_wsplit<<<256 + NSB, 256>>>(W1);              // W split + per-node init
    k_deg   <<<(EE + 255) / 256, 256>>>(EI);
    k_scan1 <<<NSB, 256>>>();
    k_gemm1 <<<G1B, 512, G1_SMEM>>>(X, B1);
    k_scan3 <<<NSB, 256>>>();                      // fused scan2+scan3
    k_fill  <<<(ET + 255) / 256, 256>>>(EI);

    // fused APPNP: fp16 features (ping-pong 0<->1, h0 in hb2) + p + 1/10 copy
    {
        int pin = 0, pob = 1;
        for (int it = 0; it < KIT; it++) {
            int last = (it == KIT - 1);
            k_diff<<<NBF2 + NBP + CPIT, 256>>>(it & 1, (it + 1) & 1, pin, pob,
                                               emb_out, last, it,
                                               (const float4*)X, (float4*)out);
            int t = pin; pin = pob; pob = t;
        }
    }

    k_gemm2<<<(NN + 15) / 16, 256>>>(emb_out, W2, B2, cls_out);
}

// round 15
// speedup vs baseline: 1.0755x; 1.0412x over previous
#include <cuda_runtime.h>
#include <cuda_fp16.h>
#include <cuda_bf16.h>
#include <cstdint>

#define NN   50000
#define EE   800000
#define ET   (EE + NN)
#define DIN  512
#define DH   128
#define DC   64
#define KIT  10
#define AL   0.1f
#define OMA  0.9f

#define NBF2 ((NN + 63) / 64)      // feature-diffusion blocks (8 warps x 8 nodes)
#define NBP  ((NN + 255) / 256)    // p-diffusion blocks
#define NSB  ((NN + 255) / 256)    // scan blocks (196)
#define G1B  ((NN + 127) / 128)    // gemm1 tiles (391)
#define CPIT 313                   // copy blocks per diffusion iteration

#define LDP    40                  // padded smem row (elements); 80B rows
#define TILE_B (128 * LDP * 2)     // bytes per smem tile (10240)
#define G1_SMEM (8 * TILE_B)       // 2 bufs x {Ah,Al,Bh,Bl} = 81920

typedef unsigned long long u64;

// ---------------- device scratch ----------------
__device__ int     g_deg[NN];
__device__ float   g_dinv[NN];
__device__ int     g_rowptr[NN + 1];
__device__ int     g_fill[NN];
__device__ __align__(16) int2 g_cw[ET];
__device__ int     g_bsum[256];
__device__ __align__(16) __nv_bfloat16 g_Whi[DH * DIN];
__device__ __align__(16) __nv_bfloat16 g_Wlo[DH * DIN];
// 0/1 = ping-pong iterates, 2 = h0 (h1 after relu), all fp16
__device__ __half2 g_hb[3][(size_t)NN * (DH/2)];
__device__ float   g_p[2][NN];

// ---------------- helpers ----------------
__device__ __forceinline__ uint32_t s2u(const void* p) {
    uint32_t a;
    asm("{ .reg .u64 t; cvta.to.shared.u64 t, %1; cvt.u32.u64 %0, t; }" : "=r"(a) : "l"(p));
    return a;
}
__device__ __forceinline__ unsigned h2u(__half2 h) {
    unsigned u; *reinterpret_cast<__half2*>(&u) = h; return u;
}
__device__ __forceinline__ unsigned b2u(__nv_bfloat162 h) {
    unsigned u; *reinterpret_cast<__nv_bfloat162*>(&u) = h; return u;
}
__device__ __forceinline__ void ldsm4(unsigned* r, uint32_t addr) {
    asm volatile("ldmatrix.sync.aligned.m8n8.x4.shared.b16 {%0,%1,%2,%3}, [%4];"
        : "=r"(r[0]), "=r"(r[1]), "=r"(r[2]), "=r"(r[3]) : "r"(addr));
}
__device__ __forceinline__ void mma16816(float* c, const unsigned* a, const unsigned* b) {
    asm volatile("mma.sync.aligned.m16n8k16.row.col.f32.bf16.bf16.f32 "
        "{%0,%1,%2,%3}, {%4,%5,%6,%7}, {%8,%9}, {%0,%1,%2,%3};"
        : "+f"(c[0]), "+f"(c[1]), "+f"(c[2]), "+f"(c[3])
        : "r"(a[0]), "r"(a[1]), "r"(a[2]), "r"(a[3]), "r"(b[0]), "r"(b[1]));
}
__device__ __forceinline__ void sts128(uint32_t addr, uint4 v) {
    asm volatile("st.shared.v4.b32 [%0], {%1,%2,%3,%4};"
        :: "r"(addr), "r"(v.x), "r"(v.y), "r"(v.z), "r"(v.w) : "memory");
}

// ---------------- preprocessing ----------------
__global__ void k_wsplit(const float* __restrict__ W1) {
    if (blockIdx.x < 256) {
        int i = blockIdx.x * 256 + threadIdx.x;
        float f = W1[i];
        __nv_bfloat16 h = __float2bfloat16_rn(f);
        g_Whi[i] = h;
        g_Wlo[i] = __float2bfloat16_rn(f - __bfloat162float(h));
    } else {
        int i = (blockIdx.x - 256) * 256 + threadIdx.x;
        if (i < NN) { g_deg[i] = 1; g_fill[i] = 0; g_p[0][i] = 1.0f; }
    }
}

__global__ void k_deg(const int* __restrict__ ei) {
    int e = blockIdx.x * blockDim.x + threadIdx.x;
    if (e < EE) atomicAdd(&g_deg[ei[EE + e]], 1);
}

__global__ void __launch_bounds__(256) k_scan1() {
    __shared__ int sh[256];
    int t = threadIdx.x;
    int i = blockIdx.x * 256 + t;
    int v = (i < NN) ? g_deg[i] : 0;
    if (i < NN) g_dinv[i] = rsqrtf((float)v);
    sh[t] = v;
    __syncthreads();
#pragma unroll
    for (int off = 1; off < 256; off <<= 1) {
        int u = (t >= off) ? sh[t - off] : 0;
        __syncthreads();
        sh[t] += u;
        __syncthreads();
    }
    if (i < NN) g_rowptr[i] = sh[t] - v;
    if (t == 255) g_bsum[blockIdx.x] = sh[255];
}

// fused scan2+scan3: each block reduces the block sums below it locally
__global__ void __launch_bounds__(256) k_scan3() {
    __shared__ int sh[256];
    int t = threadIdx.x;
    sh[t] = (t < NSB && t < (int)blockIdx.x) ? g_bsum[t] : 0;
    __syncthreads();
#pragma unroll
    for (int off = 128; off > 0; off >>= 1) {
        if (t < off) sh[t] += sh[t + off];
        __syncthreads();
    }
    int add = sh[0];
    int i = blockIdx.x * 256 + t;
    if (i < NN) g_rowptr[i] += add;
    if (blockIdx.x == 0 && t == 0) g_rowptr[NN] = ET;
}

__global__ void k_fill(const int* __restrict__ ei) {
    int idx = blockIdx.x * blockDim.x + threadIdx.x;
    if (idx >= ET) return;
    int s, d;
    if (idx < EE) { s = ei[idx]; d = ei[EE + idx]; }
    else          { s = idx - EE; d = s; }
    int pos = g_rowptr[d] + atomicAdd(&g_fill[d], 1);
    float w = g_dinv[s] * g_dinv[d];
    g_cw[pos] = make_int2(s, __float_as_int(w));
}

// ---------------- GEMM1: 512-thread pipelined HMMA (BM=128) ------------------
__global__ void __launch_bounds__(512, 1) k_gemm1(const float* __restrict__ X,
                                                  const float* __restrict__ B1) {
    extern __shared__ __align__(16) char dsm[];
    uint32_t base = s2u(dsm);

    int tid = threadIdx.x;
    int wid = tid >> 5, lane = tid & 31;
    int warp_m = wid & 3, warp_n = wid >> 2;
    int brow = blockIdx.x * 128;

    float acc[2][4][4];
#pragma unroll
    for (int mt = 0; mt < 2; mt++)
#pragma unroll
        for (int nt = 0; nt < 4; nt++)
#pragma unroll
            for (int q = 0; q < 4; q++) acc[mt][nt][q] = 0.f;

    int lrow = tid >> 2;
    int lc   = (tid & 3) * 8;
    bool xok = (brow + lrow) < NN;
    const float* xrow = X + (size_t)(brow + lrow) * DIN + lc;
    const __nv_bfloat16* whrow = g_Whi + (size_t)lrow * DIN + lc;
    const __nv_bfloat16* wlrow = g_Wlo + (size_t)lrow * DIN + lc;
    uint32_t aoff = (uint32_t)(lrow * LDP + lc) * 2;

    uint32_t a_r = warp_m * 32 + (lane & 15);
    uint32_t a_c = (lane >> 4) << 3;
    uint32_t b_r = warp_n * 32 + (lane & 7) + ((lane >> 4) << 3);
    uint32_t b_c = ((lane >> 3) & 1) << 3;

    float4 xf[2];
    uint4  whv, wlv;

    auto prefetch = [&](int s) {
        int k0 = s * 32;
        if (xok) {
            xf[0] = *(const float4*)(xrow + k0);
            xf[1] = *(const float4*)(xrow + k0 + 4);
        } else {
            xf[0] = xf[1] = make_float4(0.f, 0.f, 0.f, 0.f);
        }
        whv = *(const uint4*)(whrow + k0);
        wlv = *(const uint4*)(wlrow + k0);
    };
    auto cvstore = [&](int buf) {
        uint32_t tAh = base + (buf * 4 + 0) * TILE_B;
        uint32_t tAl = base + (buf * 4 + 1) * TILE_B;
        uint32_t tBh = base + (buf * 4 + 2) * TILE_B;
        uint32_t tBl = base + (buf * 4 + 3) * TILE_B;
        float4 f0 = xf[0], f1 = xf[1];
        __nv_bfloat162 h01 = __floats2bfloat162_rn(f0.x, f0.y);
        __nv_bfloat162 h23 = __floats2bfloat162_rn(f0.z, f0.w);
        __nv_bfloat162 h45 = __floats2bfloat162_rn(f1.x, f1.y);
        __nv_bfloat162 h67 = __floats2bfloat162_rn(f1.z, f1.w);
        float2 r01 = __bfloat1622float2(h01), r23 = __bfloat1622float2(h23);
        float2 r45 = __bfloat1622float2(h45), r67 = __bfloat1622float2(h67);
        sts128(tAh + aoff, make_uint4(b2u(h01), b2u(h23), b2u(h45), b2u(h67)));
        sts128(tAl + aoff, make_uint4(
            b2u(__floats2bfloat162_rn(f0.x - r01.x, f0.y - r01.y)),
            b2u(__floats2bfloat162_rn(f0.z - r23.x, f0.w - r23.y)),
            b2u(__floats2bfloat162_rn(f1.x - r45.x, f1.y - r45.y)),
            b2u(__floats2bfloat162_rn(f1.z - r67.x, f1.w - r67.y))));
        sts128(tBh + aoff, whv);
        sts128(tBl + aoff, wlv);
    };

    prefetch(0);
    cvstore(0);
    __syncthreads();

    for (int s = 0; s < DIN / 32; s++) {          // 16 stages
        if (s + 1 < DIN / 32) prefetch(s + 1);

        int buf = s & 1;
        uint32_t tAh = base + (buf * 4 + 0) * TILE_B;
        uint32_t tAl = base + (buf * 4 + 1) * TILE_B;
        uint32_t tBh = base + (buf * 4 + 2) * TILE_B;
        uint32_t tBl = base + (buf * 4 + 3) * TILE_B;
#pragma unroll
        for (int ks = 0; ks < 32; ks += 16) {
            unsigned Ah[2][4], Al[2][4];
#pragma unroll
            for (int mt = 0; mt < 2; mt++) {
                uint32_t off = ((a_r + mt * 16) * LDP + ks + a_c) * 2;
                ldsm4(Ah[mt], tAh + off);
                ldsm4(Al[mt], tAl + off);
            }
#pragma unroll
            for (int ntp = 0; ntp < 2; ntp++) {
                unsigned Bh[4], Bl[4];
                uint32_t off = ((b_r + ntp * 16) * LDP + ks + b_c) * 2;
                ldsm4(Bh, tBh + off);
                ldsm4(Bl, tBl + off);
#pragma unroll
                for (int mt = 0; mt < 2; mt++) {
                    mma16816(acc[mt][ntp * 2],     Ah[mt], &Bh[0]);
                    mma16816(acc[mt][ntp * 2],     Ah[mt], &Bl[0]);
                    mma16816(acc[mt][ntp * 2],     Al[mt], &Bh[0]);
                    mma16816(acc[mt][ntp * 2 + 1], Ah[mt], &Bh[2]);
                    mma16816(acc[mt][ntp * 2 + 1], Ah[mt], &Bl[2]);
                    mma16816(acc[mt][ntp * 2 + 1], Al[mt], &Bh[2]);
                }
            }
        }

        if (s + 1 < DIN / 32) {
            cvstore((s + 1) & 1);
            __syncthreads();
        }
    }

    int group = lane >> 2, tig = lane & 3;
#pragma unroll
    for (int mt = 0; mt < 2; mt++) {
#pragma unroll
        for (int nt = 0; nt < 4; nt++) {
            int col = warp_n * 32 + nt * 8 + 2 * tig;
            float bx = B1[col], by = B1[col + 1];
#pragma unroll
            for (int h = 0; h < 2; h++) {
                int row = brow + warp_m * 32 + mt * 16 + group + h * 8;
                if (row >= NN) continue;
                float v0 = fmaxf(acc[mt][nt][h * 2]     + bx, 0.f);
                float v1 = fmaxf(acc[mt][nt][h * 2 + 1] + by, 0.f);
                __half2 hv = __floats2half2_rn(v0, v1);
                size_t off = ((size_t)row << 6) + (col >> 1);
                g_hb[0][off] = hv;
                g_hb[2][off] = hv;
            }
        }
    }
}

// ---------------- fused APPNP step (gather + spread copy) --------------------
__device__ __forceinline__ void acc_edge(const __half2* __restrict__ xin,
                                         int s, float w, int lane,
                                         float& a0, float& a1, float& a2, float& a3) {
    uint2 raw = __ldg((const uint2*)(xin + ((size_t)s << 6) + (lane << 1)));
    float2 f01 = __half22float2(*reinterpret_cast<__half2*>(&raw.x));
    float2 f23 = __half22float2(*reinterpret_cast<__half2*>(&raw.y));
    a0 += w * f01.x; a1 += w * f01.y; a2 += w * f23.x; a3 += w * f23.y;
}

__global__ void __launch_bounds__(256) k_diff(int inb, int outb, int pin_i, int pout_i,
                                              float* __restrict__ emb_out, int last,
                                              int it,
                                              const float4* __restrict__ csrc,
                                              float4* __restrict__ cdst) {
    if (blockIdx.x < NBF2) {
        int wg   = (blockIdx.x << 3) + (threadIdx.x >> 5);
        int lane = threadIdx.x & 31;
        int n0 = wg << 3;
        int n1 = n0 + 8; if (n1 > NN) n1 = NN;
        const __half2* __restrict__ xin = g_hb[inb];
        for (int n = n0; n < n1; n++) {
            int beg = g_rowptr[n], end = g_rowptr[n + 1];
            float a0 = 0.f, a1 = 0.f, a2 = 0.f, a3 = 0.f;
            int e = beg;
            if ((e & 1) && e < end) {
                int2 cw = __ldg(&g_cw[e]);
                acc_edge(xin, cw.x, __int_as_float(cw.y), lane, a0, a1, a2, a3);
                e++;
            }
            for (; e + 8 <= end; e += 8) {
                int4 q0 = __ldg((const int4*)(g_cw + e));
                int4 q1 = __ldg((const int4*)(g_cw + e + 2));
                int4 q2 = __ldg((const int4*)(g_cw + e + 4));
                int4 q3 = __ldg((const int4*)(g_cw + e + 6));
                uint2 v[8];
                v[0] = __ldg((const uint2*)(xin + ((size_t)q0.x << 6) + (lane << 1)));
                v[1] = __ldg((const uint2*)(xin + ((size_t)q0.z << 6) + (lane << 1)));
                v[2] = __ldg((const uint2*)(xin + ((size_t)q1.x << 6) + (lane << 1)));
                v[3] = __ldg((const uint2*)(xin + ((size_t)q1.z << 6) + (lane << 1)));
                v[4] = __ldg((const uint2*)(xin + ((size_t)q2.x << 6) + (lane << 1)));
                v[5] = __ldg((const uint2*)(xin + ((size_t)q2.z << 6) + (lane << 1)));
                v[6] = __ldg((const uint2*)(xin + ((size_t)q3.x << 6) + (lane << 1)));
                v[7] = __ldg((const uint2*)(xin + ((size_t)q3.z << 6) + (lane << 1)));
                float wv[8] = {__int_as_float(q0.y), __int_as_float(q0.w),
                               __int_as_float(q1.y), __int_as_float(q1.w),
                               __int_as_float(q2.y), __int_as_float(q2.w),
                               __int_as_float(q3.y), __int_as_float(q3.w)};
#pragma unroll
                for (int i = 0; i < 8; i++) {
                    float2 f01 = __half22float2(*reinterpret_cast<__half2*>(&v[i].x));
                    float2 f23 = __half22float2(*reinterpret_cast<__half2*>(&v[i].y));
                    a0 += wv[i] * f01.x; a1 += wv[i] * f01.y;
                    a2 += wv[i] * f23.x; a3 += wv[i] * f23.y;
                }
            }
            for (; e + 2 <= end; e += 2) {
                int4 q = __ldg((const int4*)(g_cw + e));
                acc_edge(xin, q.x, __int_as_float(q.y), lane, a0, a1, a2, a3);
                acc_edge(xin, q.z, __int_as_float(q.w), lane, a0, a1, a2, a3);
            }
            if (e < end) {
                int2 cw = __ldg(&g_cw[e]);
                acc_edge(xin, cw.x, __int_as_float(cw.y), lane, a0, a1, a2, a3);
            }
            uint2 hraw = __ldg((const uint2*)(g_hb[2] + ((size_t)n << 6) + (lane << 1)));
            float2 h01 = __half22float2(*reinterpret_cast<__half2*>(&hraw.x));
            float2 h23 = __half22float2(*reinterpret_cast<__half2*>(&hraw.y));
            float4 o = make_float4(OMA * a0 + AL * h01.x, OMA * a1 + AL * h01.y,
                                   OMA * a2 + AL * h23.x, OMA * a3 + AL * h23.y);
            if (last) {
                *(float4*)(emb_out + ((size_t)n << 7) + (lane << 2)) = o;
            } else {
                uint2 hp;
                hp.x = h2u(__floats2half2_rn(o.x, o.y));
                hp.y = h2u(__floats2half2_rn(o.z, o.w));
                *(uint2*)(&g_hb[outb][((size_t)n << 6) + (lane << 1)]) = hp;
            }
        }
    } else if (blockIdx.x < NBF2 + NBP) {
        int v = (blockIdx.x - NBF2) * 256 + threadIdx.x;
        if (v >= NN) return;
        const float* __restrict__ pin = g_p[pin_i];
        float acc = 0.f;
        int beg = g_rowptr[v], end = g_rowptr[v + 1];
        int e = beg;
        if ((e & 1) && e < end) {
            int2 cw = __ldg(&g_cw[e]);
            acc += __int_as_float(cw.y) * __ldg(&pin[cw.x]);
            e++;
        }
        for (; e + 4 <= end; e += 4) {
            int4 q0 = __ldg((const int4*)(g_cw + e));
            int4 q1 = __ldg((const int4*)(g_cw + e + 2));
            float p0 = __ldg(&pin[q0.x]), p1 = __ldg(&pin[q0.z]);
            float p2 = __ldg(&pin[q1.x]), p3 = __ldg(&pin[q1.z]);
            acc += __int_as_float(q0.y) * p0 + __int_as_float(q0.w) * p1
                 + __int_as_float(q1.y) * p2 + __int_as_float(q1.w) * p3;
        }
        for (; e < end; e++) {
            int2 cw = __ldg(&g_cw[e]);
            acc += __int_as_float(cw.y) * __ldg(&pin[cw.x]);
        }
        g_p[pout_i][v] = OMA * acc + AL;
    } else {
        // x-passthrough copy, 1/10th per iteration: CPIT blocks x 2048 float4
        int b = it * CPIT + (blockIdx.x - NBF2 - NBP);
        int i = b * 2048 + threadIdx.x;
#pragma unroll
        for (int r = 0; r < 8; r++) {
            int idx = i + r * 256;
            if (idx < NN * DIN / 4) cdst[idx] = csrc[idx];
        }
    }
}

// ---------------- GEMM2: out = emb1 @ W2^T + p * b2^T ----------------
__global__ void __launch_bounds__(256) k_gemm2(const float* __restrict__ EMB,
                                               const float* __restrict__ W2,
                                               const float* __restrict__ B2,
                                               float* __restrict__ out) {
    __shared__ float wst[DH][DC + 4];
    __shared__ float xs[16][DH];
    int tid = threadIdx.x;
#pragma unroll
    for (int i = 0; i < 8; i++) {
        int slot = tid + i * 256;
        int j = slot >> 5, k4 = slot & 31;
        float4 v = *(const float4*)(W2 + (size_t)j * DH + k4 * 4);
        wst[k4 * 4 + 0][j] = v.x; wst[k4 * 4 + 1][j] = v.y;
        wst[k4 * 4 + 2][j] = v.z; wst[k4 * 4 + 3][j] = v.w;
    }
    int n0 = blockIdx.x * 16;
#pragma unroll
    for (int i = 0; i < 2; i++) {
        int slot = tid + i * 256;
        int r = slot >> 5, k4 = slot & 31;
        int gn = n0 + r;
        float4 v = (gn < NN) ? *(const float4*)(EMB + (size_t)gn * DH + k4 * 4)
                             : make_float4(0.f, 0.f, 0.f, 0.f);
        *(float4*)&xs[r][k4 * 4] = v;
    }
    __syncthreads();
    int nl = tid >> 4, jg = tid & 15;
    float a0 = 0.f, a1 = 0.f, a2 = 0.f, a3 = 0.f;
#pragma unroll
    for (int k = 0; k < DH; k++) {
        float xv = xs[nl][k];
        float4 wv = *(const float4*)&wst[k][jg * 4];
        a0 += xv * wv.x; a1 += xv * wv.y; a2 += xv * wv.z; a3 += xv * wv.w;
    }
    int gn = n0 + nl;
    if (gn < NN) {
        float pv = g_p[0][gn];
        float4 bv = *(const float4*)(B2 + jg * 4);
        float4 o = make_float4(a0 + pv * bv.x, a1 + pv * bv.y,
                               a2 + pv * bv.z, a3 + pv * bv.w);
        *(float4*)(out + (size_t)gn * DC + jg * 4) = o;
    }
}

// ---------------- host launcher ----------------
extern "C" void kernel_launch(void* const* d_in, const int* in_sizes, int n_in,
                              void* d_out, int out_size) {
    const float* X  = (const float*)d_in[0];
    const int*   EI = (const int*)  d_in[1];
    const float* W1 = (const float*)d_in[2];
    const float* B1 = (const float*)d_in[3];
    const float* W2 = (const float*)d_in[4];
    const float* B2 = (const float*)d_in[5];
    float* out = (float*)d_out;
    float* emb_out = out + (size_t)NN * DIN;
    float* cls_out = out + (size_t)NN * (DIN + DH);

    cudaFuncSetAttribute(k_gemm1, cudaFuncAttributeMaxDynamicSharedMemorySize, G1_SMEM);

    // Side stream for the graph-prep branch (runs concurrently with k_gemm1).
    // NOT destroyed here: destroying a stream/event that has joined an active
    // stream capture would invalidate the capture. Host-side only; no device
    // memory involved. Created fresh each call (deterministic work).
    cudaStream_t s1;
    cudaStreamCreateWithFlags(&s1, cudaStreamNonBlocking);
    cudaEvent_t ev0, ev1;
    cudaEventCreateWithFlags(&ev0, cudaEventDisableTiming);
    cudaEventCreateWithFlags(&ev1, cudaEventDisableTiming);

    // launch 1 (main): W split + per-node init (needed by BOTH branches)
    k_wsplit<<<256 + NSB, 256>>>(W1);
    cudaEventRecord(ev0, 0);
    cudaStreamWaitEvent(s1, ev0, 0);

    // prep branch on s1: deg -> scan1 -> scan3 -> fill
    k_deg  <<<(EE + 255) / 256, 256, 0, s1>>>(EI);    // launch 2
    k_scan1<<<NSB, 256, 0, s1>>>();                   // launch 3

    // main branch: gemm1 (launch 4 = profiler slot), overlaps the prep branch
    k_gemm1<<<G1B, 512, G1_SMEM>>>(X, B1);

    k_scan3<<<NSB, 256, 0, s1>>>();                   // launch 5
    k_fill <<<(ET + 255) / 256, 256, 0, s1>>>(EI);    // launch 6
    cudaEventRecord(ev1, s1);
    cudaStreamWaitEvent(0, ev1, 0);                   // join before diffusion

    // fused APPNP: fp16 features (ping-pong 0<->1, h0 in hb2) + p + 1/10 copy
    {
        int pin = 0, pob = 1;
        for (int it = 0; it < KIT; it++) {
            int last = (it == KIT - 1);
            k_diff<<<NBF2 + NBP + CPIT, 256>>>(it & 1, (it + 1) & 1, pin, pob,
                                               emb_out, last, it,
                                               (const float4*)X, (float4*)out);
            int t = pin; pin = pob; pob = t;
        }
    }

    k_gemm2<<<(NN + 15) / 16, 256>>>(emb_out, W2, B2, cls_out);
}